// round 1
// baseline (speedup 1.0000x reference)
#include <cuda_runtime.h>

// Dynamic grouped conv, algebraically reduced:
//   out[b,o,h,w] = sum_{kh,kw} ker[b,o,kh,kw] * S[b,g,h+kh,w+kw]
//   S[b,g] = sum of the 8 input channels of group g (reflection-padded)
// ker[b, o, kh, kw] = leaky_relu(rep[b,:] @ W[(o*9+kh*3+kw), :], 0.1)

static constexpr int HH = 256;
static constexpr int WW = 256;
static constexpr int IN_CH = 64;
static constexpr int OUT_CH = 64;
static constexpr int GROUPS = 8;
static constexpr int FPG = 8;
static constexpr int TH = 64;
static constexpr int TW = 64;
static constexpr int SSTRIDE = TW + 4;   // 68: row stride in smem tile

__device__ __forceinline__ int refl(int i, int n) {
    // reflection pad=1: only -1 and n can occur, but keep general form
    i = (i < 0) ? -i : i;
    return (i >= n) ? (2 * n - 2 - i) : i;
}

__global__ __launch_bounds__(256, 2)
void dynconv_fused(const float* __restrict__ x,
                   const float* __restrict__ rep,
                   const float* __restrict__ Wm,
                   float* __restrict__ out) {
    __shared__ float S[(TH + 2) * SSTRIDE];
    __shared__ float wk[FPG * 9];          // 8 output channels x 9 taps

    const int bz = blockIdx.z;             // b*8 + g
    const int b  = bz >> 3;
    const int g  = bz & 7;
    const int ty0 = blockIdx.y * TH;
    const int tx0 = blockIdx.x * TW;
    const int tid = threadIdx.x;

    // ---- threads 0..71: generate this block's 72 dynamic weights ----
    if (tid < FPG * 9) {
        const int j = (g * FPG) * 9 + tid;          // row of W (576 x 32)
        const float* r = rep + b * 32;
        const float* w = Wm + j * 32;
        float acc = 0.f;
        #pragma unroll
        for (int i = 0; i < 32; i++) acc = fmaf(r[i], w[i], acc);
        wk[tid] = (acc > 0.f) ? acc : 0.1f * acc;
    }

    // ---- group-sum into padded SMEM tile (reflection pad at borders) ----
    const float* xb = x + (size_t)(b * IN_CH + g * FPG) * (HH * WW);
    for (int pos = tid; pos < (TH + 2) * (TW + 2); pos += 256) {
        const int r = pos / (TW + 2);
        const int c = pos - r * (TW + 2);
        const int gy = refl(ty0 + r - 1, HH);
        const int gx = refl(tx0 + c - 1, WW);
        const float* p = xb + gy * WW + gx;
        float acc = 0.f;
        #pragma unroll
        for (int f = 0; f < FPG; f++) acc += p[f * (HH * WW)];
        S[r * SSTRIDE + c] = acc;
    }
    __syncthreads();

    // ---- weights to registers (same for all threads; 72 regs) ----
    float wreg[FPG][9];
    #pragma unroll
    for (int o = 0; o < FPG; o++)
        #pragma unroll
        for (int k = 0; k < 9; k++)
            wreg[o][k] = wk[o * 9 + k];

    // ---- stencil: each thread owns one column (px), 16 rows ----
    const int px = tid & 63;
    const int py0 = (tid >> 6) * 16;       // 0,16,32,48
    float* ob = out + ((size_t)(b * OUT_CH + g * FPG) * HH + ty0) * WW + tx0;

    for (int j = 0; j < 16; j++) {
        const int py = py0 + j;
        float s[9];
        #pragma unroll
        for (int kh = 0; kh < 3; kh++)
            #pragma unroll
            for (int kw = 0; kw < 3; kw++)
                s[kh * 3 + kw] = S[(py + kh) * SSTRIDE + px + kw];

        #pragma unroll
        for (int o = 0; o < FPG; o++) {
            float acc = 0.f;
            #pragma unroll
            for (int k = 0; k < 9; k++) acc = fmaf(wreg[o][k], s[k], acc);
            ob[(size_t)o * (HH * WW) + py * WW + px] = acc;
        }
    }
}

extern "C" void kernel_launch(void* const* d_in, const int* in_sizes, int n_in,
                              void* d_out, int out_size) {
    const float* x   = (const float*)d_in[0];
    const float* rep = (const float*)d_in[1];
    const float* Wm  = (const float*)d_in[2];
    float* out = (float*)d_out;

    dim3 grid(WW / TW, HH / TH, 8 * GROUPS);   // 4 x 4 x 64 = 1024 blocks
    dynconv_fused<<<grid, 256>>>(x, rep, Wm, out);
}

// round 2
// speedup vs baseline: 1.2355x; 1.2355x over previous
#include <cuda_runtime.h>

// Dynamic grouped conv, algebraically reduced:
//   out[b,o,h,w] = sum_{kh,kw} ker[b,o,kh,kw] * S[b,g,h+kh,w+kw]
//   S[b,g] = sum of the 8 input channels of group g (reflection-padded)
// ker[b, o, kh, kw] = leaky_relu(rep[b,:] @ W[(o*9+kh*3+kw), :], 0.1)
//
// R2: split 8 output channels across 2 thread-groups (36 weight regs/thread
// instead of 72) to cut regs 96 -> <=64 and raise occupancy 2 -> 4 CTA/SM.

static constexpr int HH = 256;
static constexpr int WW = 256;
static constexpr int IN_CH = 64;
static constexpr int OUT_CH = 64;
static constexpr int GROUPS = 8;
static constexpr int FPG = 8;
static constexpr int TH = 64;
static constexpr int TW = 64;
static constexpr int SSTRIDE = TW + 4;   // 68: row stride in smem tile

__device__ __forceinline__ int refl(int i, int n) {
    i = (i < 0) ? -i : i;
    return (i >= n) ? (2 * n - 2 - i) : i;
}

__global__ __launch_bounds__(256, 4)
void dynconv_fused(const float* __restrict__ x,
                   const float* __restrict__ rep,
                   const float* __restrict__ Wm,
                   float* __restrict__ out) {
    __shared__ float S[(TH + 2) * SSTRIDE];
    __shared__ float wk[FPG * 9];          // 8 output channels x 9 taps

    const int bz = blockIdx.z;             // b*8 + g
    const int b  = bz >> 3;
    const int g  = bz & 7;
    const int ty0 = blockIdx.y * TH;
    const int tx0 = blockIdx.x * TW;
    const int tid = threadIdx.x;

    // ---- threads 0..71: generate this block's 72 dynamic weights ----
    if (tid < FPG * 9) {
        const int j = (g * FPG) * 9 + tid;          // row of W (576 x 32)
        const float* r = rep + b * 32;
        const float* w = Wm + j * 32;
        float acc = 0.f;
        #pragma unroll
        for (int i = 0; i < 32; i++) acc = fmaf(r[i], w[i], acc);
        wk[tid] = (acc > 0.f) ? acc : 0.1f * acc;
    }

    // ---- group-sum into padded SMEM tile (reflection pad at borders) ----
    const float* xb = x + (size_t)(b * IN_CH + g * FPG) * (HH * WW);
    for (int pos = tid; pos < (TH + 2) * (TW + 2); pos += 256) {
        const int r = pos / (TW + 2);
        const int c = pos - r * (TW + 2);
        const int gy = refl(ty0 + r - 1, HH);
        const int gx = refl(tx0 + c - 1, WW);
        const float* p = xb + gy * WW + gx;
        float acc = 0.f;
        #pragma unroll
        for (int f = 0; f < FPG; f++) acc += p[f * (HH * WW)];
        S[r * SSTRIDE + c] = acc;
    }
    __syncthreads();

    // ---- thread mapping: 64 cols x (2 row-halves x 2 channel-halves) ----
    const int px      = tid & 63;
    const int grp     = tid >> 6;          // 0..3
    const int chhalf  = grp & 1;           // 0: ch 0-3, 1: ch 4-7
    const int rowhalf = grp >> 1;          // 0: rows 0-31, 1: rows 32-63
    const int py0     = rowhalf * 32;

    // 4 channels x 9 taps = 36 weight regs (uniform within each half)
    float wreg[4][9];
    #pragma unroll
    for (int o = 0; o < 4; o++)
        #pragma unroll
        for (int k = 0; k < 9; k++)
            wreg[o][k] = wk[(chhalf * 4 + o) * 9 + k];

    float* ob = out + ((size_t)(b * OUT_CH + g * FPG + chhalf * 4) * HH + ty0) * WW + tx0;

    for (int j = 0; j < 32; j++) {
        const int py = py0 + j;
        float s[9];
        #pragma unroll
        for (int kh = 0; kh < 3; kh++)
            #pragma unroll
            for (int kw = 0; kw < 3; kw++)
                s[kh * 3 + kw] = S[(py + kh) * SSTRIDE + px + kw];

        #pragma unroll
        for (int o = 0; o < 4; o++) {
            float acc = 0.f;
            #pragma unroll
            for (int k = 0; k < 9; k++) acc = fmaf(wreg[o][k], s[k], acc);
            ob[(size_t)o * (HH * WW) + py * WW + px] = acc;
        }
    }
}

extern "C" void kernel_launch(void* const* d_in, const int* in_sizes, int n_in,
                              void* d_out, int out_size) {
    const float* x   = (const float*)d_in[0];
    const float* rep = (const float*)d_in[1];
    const float* Wm  = (const float*)d_in[2];
    float* out = (float*)d_out;

    dim3 grid(WW / TW, HH / TH, 8 * GROUPS);   // 4 x 4 x 64 = 1024 blocks
    dynconv_fused<<<grid, 256>>>(x, rep, Wm, out);
}